// round 8
// baseline (speedup 1.0000x reference)
#include <cuda_runtime.h>
#include <cuda_bf16.h>
#include <mma.h>
#include <cstdint>
#include <cstddef>
#include <math.h>
#include <float.h>

using namespace nvcuda;

#define VSZ 30000
#define VPAD 30080
#define HSZ 512
#define BSZ 16
#define SSZ 256
#define JSZ 10
#define TSZ 8
#define NOPS 4
#define RSZ (JSZ*BSZ)
#define NEGV (-1e9f)
#define NCTA 235
#define NCTAP 240

// fp32 state
__device__ float g_w[RSZ*HSZ];
__device__ float g_hA[RSZ*HSZ];
__device__ float g_hB[RSZ*HSZ];
__device__ float g_part[4*RSZ*3072];
__device__ float g_logits[RSZ*VSZ];
__device__ float g_pmax[RSZ*NCTAP];
__device__ float g_psum[RSZ*NCTAP];
// bf16 hi/lo splits for tensor-core vocab GEMM
__device__ __nv_bfloat16 g_ehi[(size_t)VPAD*HSZ];
__device__ __nv_bfloat16 g_elo[(size_t)VPAD*HSZ];
__device__ __nv_bfloat16 g_hh[RSZ*HSZ];
__device__ __nv_bfloat16 g_hl[RSZ*HSZ];

// ---------------- cp.async helpers (sm_80 baseline ISA) ----------------
__device__ __forceinline__ uint32_t smem_to_u32(const void* smem_ptr) {
    uint32_t addr;
    asm("{ .reg .u64 tmp; cvta.to.shared.u64 tmp, %1; cvt.u32.u64 %0, tmp; }"
        : "=r"(addr) : "l"(smem_ptr));
    return addr;
}
__device__ __forceinline__ void cp_async16(uint32_t saddr, const void* gptr) {
    asm volatile("cp.async.cg.shared.global [%0], [%1], 16;"
                 :: "r"(saddr), "l"(gptr) : "memory");
}
#define CP_COMMIT() asm volatile("cp.async.commit_group;" ::: "memory")
#define CP_WAIT0()  asm volatile("cp.async.wait_group 0;" ::: "memory")

// ---------------- init ----------------
__global__ __launch_bounds__(256)
void k_init(const float* __restrict__ slot, const float* __restrict__ ehid) {
    int i = blockIdx.x*blockDim.x + threadIdx.x;
    if (i < RSZ*HSZ) {
        int r = i / HSZ, h = i - r*HSZ;
        int j = r / BSZ, b = r - j*BSZ;
        g_w[i]  = slot[j*HSZ + h];
        g_hA[i] = ehid[b*HSZ + h];
    }
}

// split emb into bf16 hi/lo, pad rows >= VSZ with zero
__global__ __launch_bounds__(256)
void k_split_emb(const float* __restrict__ emb) {
    size_t i = (size_t)blockIdx.x*blockDim.x + threadIdx.x;
    if (i >= (size_t)VPAD*HSZ) return;
    size_t row = i / HSZ;
    float v = (row < VSZ) ? emb[i] : 0.f;
    __nv_bfloat16 hi = __float2bfloat16_rn(v);
    float lo = v - __bfloat162float(hi);
    g_ehi[i] = hi;
    g_elo[i] = __float2bfloat16_rn(lo);
}

// ---------------- GRU GEMM (split-K=4) ----------------
__global__ __launch_bounds__(256)
void k_gru_gemm(const float* __restrict__ Wih,
                const float* __restrict__ Whh, int parity) {
    const float* __restrict__ hold = parity ? g_hB : g_hA;
    int n0 = blockIdx.x * 128, m0 = blockIdx.y * 80, z = blockIdx.z;
    const float* __restrict__ A  = (n0 < 1536) ? g_w : hold;
    const float* __restrict__ Bm = (n0 < 1536) ? Wih : Whh;
    int bc0 = (n0 < 1536) ? n0 : (n0 - 1536);
    __shared__ float As[32][81];
    __shared__ float Bs[32][129];
    int tid = threadIdx.x, tx = tid & 15, ty = tid >> 4;
    float acc[5][8];
    #pragma unroll
    for (int i = 0; i < 5; i++)
        #pragma unroll
        for (int j = 0; j < 8; j++) acc[i][j] = 0.f;
    for (int kt = 0; kt < 4; kt++) {
        int k0 = z*128 + kt*32;
        #pragma unroll
        for (int i = 0; i < 10; i++) {
            int idx = tid + 256*i; int m = idx >> 5, kk = idx & 31;
            As[kk][m] = A[(m0+m)*HSZ + k0 + kk];
        }
        #pragma unroll
        for (int i = 0; i < 16; i++) {
            int idx = tid + 256*i; int n = idx >> 5, kk = idx & 31;
            Bs[kk][n] = Bm[(bc0+n)*HSZ + k0 + kk];
        }
        __syncthreads();
        #pragma unroll
        for (int kk = 0; kk < 32; kk++) {
            float a[5], bb[8];
            #pragma unroll
            for (int i = 0; i < 5; i++) a[i] = As[kk][ty + 16*i];
            #pragma unroll
            for (int j = 0; j < 8; j++) bb[j] = Bs[kk][tx + 16*j];
            #pragma unroll
            for (int i = 0; i < 5; i++)
                #pragma unroll
                for (int j = 0; j < 8; j++) acc[i][j] += a[i]*bb[j];
        }
        __syncthreads();
    }
    float* P = g_part + (size_t)z*(RSZ*3072);
    #pragma unroll
    for (int i = 0; i < 5; i++)
        #pragma unroll
        for (int j = 0; j < 8; j++)
            P[(m0+ty+16*i)*3072 + n0 + tx + 16*j] = acc[i][j];
}

// ---------------- GRU gate + h bf16 split ----------------
__global__ __launch_bounds__(512)
void k_gru_gate(const float* __restrict__ bih,
                const float* __restrict__ bhh, int parity) {
    const float* __restrict__ hold = parity ? g_hB : g_hA;
    float* __restrict__ hnew = parity ? g_hA : g_hB;
    int r = blockIdx.x, c = threadIdx.x;
    float ir=0.f, iz=0.f, inn=0.f, hr=0.f, hz=0.f, hn=0.f;
    #pragma unroll
    for (int z = 0; z < 4; z++) {
        const float* P = g_part + (size_t)z*(RSZ*3072) + (size_t)r*3072;
        ir += P[c]; iz += P[512+c]; inn += P[1024+c];
        hr += P[1536+c]; hz += P[2048+c]; hn += P[2560+c];
    }
    ir += bih[c]; iz += bih[512+c]; inn += bih[1024+c];
    hr += bhh[c]; hz += bhh[512+c]; hn += bhh[1024+c];
    float rg = 1.f/(1.f+expf(-(ir+hr)));
    float zg = 1.f/(1.f+expf(-(iz+hz)));
    float ng = tanhf(inn + rg*hn);
    float v = (1.f-zg)*ng + zg*hold[r*HSZ+c];
    hnew[r*HSZ+c] = v;
    __nv_bfloat16 hi = __float2bfloat16_rn(v);
    float lo = v - __bfloat162float(hi);
    g_hh[r*HSZ+c] = hi;
    g_hl[r*HSZ+c] = __float2bfloat16_rn(lo);
}

// ---------------- wmma bf16 vocab GEMM + partial-softmax epilogue --------
// grid 235, block 256 (8 warps). CTA tile: 128 v x 160 r, K=512, hi/lo 3-pass.
#define LDA 72
#define A_SPL (128*LDA*2)
#define B_SPL (160*LDA*2)
#define OFF_AHI 0
#define OFF_ALO (A_SPL)
#define OFF_BHI (2*A_SPL)
#define OFF_BLO (2*A_SPL + B_SPL)
#define SBUF    (2*A_SPL + 2*B_SPL)
#define VW_SMEM (2*SBUF)
#define LDS_T 140   /* epilogue tile ld (multiple of 4 for wmma float store) */

__global__ __launch_bounds__(256)
void k_vocab_wmma() {
    extern __shared__ char smem[];
    uint32_t sb = smem_to_u32(smem);
    int tid = threadIdx.x, wid = tid >> 5;
    int wr = wid >> 1, wc = wid & 1;
    size_t vbase = (size_t)blockIdx.x * 128;

    const uint4* Ehi = (const uint4*)g_ehi;
    const uint4* Elo = (const uint4*)g_elo;
    const uint4* Hhi = (const uint4*)g_hh;
    const uint4* Hlo = (const uint4*)g_hl;

    wmma::fragment<wmma::accumulator, 16, 16, 16, float> acc[2][5];
    #pragma unroll
    for (int i = 0; i < 2; i++)
        #pragma unroll
        for (int j = 0; j < 5; j++) wmma::fill_fragment(acc[i][j], 0.f);

    {
        uint32_t base = sb;
        #pragma unroll
        for (int it = 0; it < 4; it++) {
            int idx = tid + 256*it;
            int row = idx >> 3, q = idx & 7;
            uint32_t so = (uint32_t)(row*LDA + q*8) * 2u;
            size_t gi = (vbase + (size_t)row) * 64 + (size_t)q;
            cp_async16(base + OFF_AHI + so, Ehi + gi);
            cp_async16(base + OFF_ALO + so, Elo + gi);
        }
        #pragma unroll
        for (int it = 0; it < 5; it++) {
            int idx = tid + 256*it;
            if (idx < 1280) {
                int row = idx >> 3, q = idx & 7;
                uint32_t so = (uint32_t)(row*LDA + q*8) * 2u;
                size_t gi = (size_t)row * 64 + (size_t)q;
                cp_async16(base + OFF_BHI + so, Hhi + gi);
                cp_async16(base + OFF_BLO + so, Hlo + gi);
            }
        }
        CP_COMMIT();
    }

    for (int c = 0; c < 8; c++) {
        CP_WAIT0();
        __syncthreads();
        if (c < 7) {
            uint32_t base = sb + ((c + 1) & 1) * SBUF;
            int cq = (c + 1) * 8;
            #pragma unroll
            for (int it = 0; it < 4; it++) {
                int idx = tid + 256*it;
                int row = idx >> 3, q = idx & 7;
                uint32_t so = (uint32_t)(row*LDA + q*8) * 2u;
                size_t gi = (vbase + (size_t)row) * 64 + (size_t)(cq + q);
                cp_async16(base + OFF_AHI + so, Ehi + gi);
                cp_async16(base + OFF_ALO + so, Elo + gi);
            }
            #pragma unroll
            for (int it = 0; it < 5; it++) {
                int idx = tid + 256*it;
                if (idx < 1280) {
                    int row = idx >> 3, q = idx & 7;
                    uint32_t so = (uint32_t)(row*LDA + q*8) * 2u;
                    size_t gi = (size_t)row * 64 + (size_t)(cq + q);
                    cp_async16(base + OFF_BHI + so, Hhi + gi);
                    cp_async16(base + OFF_BLO + so, Hlo + gi);
                }
            }
            CP_COMMIT();
        }
        const __nv_bfloat16* pAhi = (const __nv_bfloat16*)(smem + (c & 1)*SBUF + OFF_AHI);
        const __nv_bfloat16* pAlo = (const __nv_bfloat16*)(smem + (c & 1)*SBUF + OFF_ALO);
        const __nv_bfloat16* pBhi = (const __nv_bfloat16*)(smem + (c & 1)*SBUF + OFF_BHI);
        const __nv_bfloat16* pBlo = (const __nv_bfloat16*)(smem + (c & 1)*SBUF + OFF_BLO);
        #pragma unroll
        for (int kk = 0; kk < 4; kk++) {
            wmma::fragment<wmma::matrix_a, 16, 16, 16, __nv_bfloat16, wmma::row_major> a0h, a1h, a0l, a1l;
            wmma::load_matrix_sync(a0h, pAhi + (wr*32)      * LDA + kk*16, LDA);
            wmma::load_matrix_sync(a1h, pAhi + (wr*32 + 16) * LDA + kk*16, LDA);
            wmma::load_matrix_sync(a0l, pAlo + (wr*32)      * LDA + kk*16, LDA);
            wmma::load_matrix_sync(a1l, pAlo + (wr*32 + 16) * LDA + kk*16, LDA);
            #pragma unroll
            for (int j = 0; j < 5; j++) {
                int nb = wc*80 + j*16;
                wmma::fragment<wmma::matrix_b, 16, 16, 16, __nv_bfloat16, wmma::col_major> bh, bl;
                wmma::load_matrix_sync(bh, pBhi + nb*LDA + kk*16, LDA);
                wmma::mma_sync(acc[0][j], a0h, bh, acc[0][j]);
                wmma::mma_sync(acc[1][j], a1h, bh, acc[1][j]);
                wmma::mma_sync(acc[0][j], a0l, bh, acc[0][j]);
                wmma::mma_sync(acc[1][j], a1l, bh, acc[1][j]);
                wmma::load_matrix_sync(bl, pBlo + nb*LDA + kk*16, LDA);
                wmma::mma_sync(acc[0][j], a0h, bl, acc[0][j]);
                wmma::mma_sync(acc[1][j], a1h, bl, acc[1][j]);
            }
        }
        __syncthreads();
    }

    // epilogue: stage D[v][n] into smem S[n*LDS_T + v], compute per-n partial
    // max/sumexp over this CTA's v-rows, write logits coalesced.
    float* S = (float*)smem;
    #pragma unroll
    for (int i = 0; i < 2; i++)
        #pragma unroll
        for (int j = 0; j < 5; j++)
            wmma::store_matrix_sync(S + (size_t)(wc*80 + j*16)*LDS_T + (wr*32 + i*16),
                                    acc[i][j], LDS_T, wmma::mem_col_major);
    __syncthreads();
    int vlim = (int)VSZ - (int)vbase; if (vlim > 128) vlim = 128;
    if (tid < 160) {
        const float* col = S + (size_t)tid*LDS_T;
        float mx = -FLT_MAX;
        for (int v = 0; v < vlim; v++) mx = fmaxf(mx, col[v]);
        float sm = 0.f;
        for (int v = 0; v < vlim; v++) sm += expf(col[v]-mx);
        g_pmax[tid*NCTAP + blockIdx.x] = mx;
        g_psum[tid*NCTAP + blockIdx.x] = sm;
    }
    for (int idx = tid; idx < 160*128; idx += 256) {
        int n = idx >> 7, v = idx & 127;
        if (v < vlim)
            g_logits[(size_t)n*VSZ + vbase + v] = S[(size_t)n*LDS_T + v];
    }
}

// ---------------- fused attn + single-pass softmax + scatter + argmax -----
// grid 160 (one block per r), block 512
__global__ __launch_bounds__(512)
void k_attn_softmax(const int* __restrict__ x, const float* __restrict__ enc,
                    const float* __restrict__ wgenW, const float* __restrict__ wgenb,
                    const float* __restrict__ actW, const float* __restrict__ actb,
                    const float* __restrict__ emb, float* __restrict__ out,
                    int is_t0, int parity, int t, int ptoff) {
    const float* __restrict__ hnew = parity ? g_hA : g_hB;
    int r = blockIdx.x, tid = threadIdx.x, lane = tid & 31, warp = tid >> 5;
    int j = r / BSZ, b = r % BSZ;
    __shared__ float hs[HSZ];
    __shared__ float att[SSZ];
    __shared__ int   xs[SSZ];
    __shared__ float red[512];
    __shared__ int   redi[512];
    __shared__ float s_pg, s_bv;
    __shared__ int   s_bi, s_widx;

    hs[tid] = hnew[(size_t)r*HSZ + tid];
    if (tid < SSZ) xs[tid] = x[b*SSZ + tid];
    __syncthreads();

    // ---- attention scores ----
    const float4* hv = (const float4*)hs;
    float4 h0 = hv[lane], h1 = hv[lane+32], h2 = hv[lane+64], h3 = hv[lane+96];
    #pragma unroll 4
    for (int i = 0; i < 16; i++) {
        int s = warp*16 + i;
        const float4* ev = (const float4*)(enc + ((size_t)b*SSZ + s)*HSZ);
        float4 e0 = ev[lane], e1 = ev[lane+32], e2 = ev[lane+64], e3 = ev[lane+96];
        float v = e0.x*h0.x + e0.y*h0.y + e0.z*h0.z + e0.w*h0.w
                + e1.x*h1.x + e1.y*h1.y + e1.z*h1.z + e1.w*h1.w
                + e2.x*h2.x + e2.y*h2.y + e2.z*h2.z + e2.w*h2.w
                + e3.x*h3.x + e3.y*h3.y + e3.z*h3.z + e3.w*h3.w;
        #pragma unroll
        for (int off = 16; off > 0; off >>= 1)
            v += __shfl_xor_sync(0xffffffffu, v, off);
        if (lane == 0) att[s] = (xs[s] == 0) ? NEGV : v;
    }
    __syncthreads();

    // ---- softmax over S=256 ----
    float mv = (tid < SSZ) ? att[tid] : -FLT_MAX;
    red[tid] = mv; __syncthreads();
    #pragma unroll
    for (int off = 256; off > 0; off >>= 1) {
        if (tid < off) red[tid] = fmaxf(red[tid], red[tid+off]);
        __syncthreads();
    }
    float amx = red[0]; __syncthreads();
    float ex = (tid < SSZ) ? expf(mv - amx) : 0.f;
    red[tid] = ex; __syncthreads();
    #pragma unroll
    for (int off = 256; off > 0; off >>= 1) {
        if (tid < off) red[tid] += red[tid+off];
        __syncthreads();
    }
    float ainv = 1.f/red[0]; __syncthreads();
    if (tid < SSZ) att[tid] = ex*ainv;
    __syncthreads();

    // ---- context (thread owns column tid) ----
    float ctx = 0.f;
    const float* eb = enc + (size_t)b*SSZ*HSZ + tid;
    #pragma unroll 8
    for (int s = 0; s < SSZ; s++) ctx += att[s]*eb[(size_t)s*HSZ];

    // ---- p_gen ----
    float pv = g_w[(size_t)r*HSZ+tid]*wgenW[tid]
             + hs[tid]*wgenW[HSZ+tid]
             + ctx*wgenW[2*HSZ+tid];
    red[tid] = pv; __syncthreads();
    #pragma unroll
    for (int off = 256; off > 0; off >>= 1) {
        if (tid < off) red[tid] += red[tid+off];
        __syncthreads();
    }
    if (tid == 0) s_pg = 1.f/(1.f+expf(-(red[0] + wgenb[0])));

    // ---- gate head at t==0 ----
    if (is_t0) {
        #pragma unroll
        for (int op = 0; op < NOPS; op++) {
            __syncthreads();
            red[tid] = ctx*actW[op*HSZ + tid]; __syncthreads();
            #pragma unroll
            for (int off = 256; off > 0; off >>= 1) {
                if (tid < off) red[tid] += red[tid+off];
                __syncthreads();
            }
            if (tid == 0) out[b*JSZ*NOPS + j*NOPS + op] = red[0] + actb[op];
        }
    }
    __syncthreads();

    // ---- reduce vocab-GEMM partials -> global max/sum over V ----
    float pm = (tid < NCTA) ? g_pmax[r*NCTAP + tid] : -FLT_MAX;
    red[tid] = pm; __syncthreads();
    #pragma unroll
    for (int off = 256; off > 0; off >>= 1) {
        if (tid < off) red[tid] = fmaxf(red[tid], red[tid+off]);
        __syncthreads();
    }
    float mx = red[0]; __syncthreads();
    float ps = (tid < NCTA) ? g_psum[r*NCTAP + tid]*expf(pm - mx) : 0.f;
    red[tid] = ps; __syncthreads();
    #pragma unroll
    for (int off = 256; off > 0; off >>= 1) {
        if (tid < off) red[tid] += red[tid+off];
        __syncthreads();
    }
    float sm = red[0]; __syncthreads();

    float pg = s_pg;
    float scale = pg / sm;
    const float4* __restrict__ L4 = (const float4*)(g_logits + (size_t)r*VSZ);
    float* ob = out + ptoff + ((size_t)(b*JSZ + j)*TSZ + t)*VSZ;
    float4* ob4 = (float4*)ob;

    // ---- single pass: write p, track base argmax ----
    float bv = -1.f; int bi = 0;
    for (int i = tid; i < VSZ/4; i += 512) {
        float4 q = L4[i];
        float4 p;
        p.x = expf(q.x-mx)*scale; p.y = expf(q.y-mx)*scale;
        p.z = expf(q.z-mx)*scale; p.w = expf(q.w-mx)*scale;
        ob4[i] = p;
        if (p.x > bv) { bv = p.x; bi = 4*i; }
        if (p.y > bv) { bv = p.y; bi = 4*i+1; }
        if (p.z > bv) { bv = p.z; bi = 4*i+2; }
        if (p.w > bv) { bv = p.w; bi = 4*i+3; }
    }
    red[tid] = bv; redi[tid] = bi; __syncthreads();
    #pragma unroll
    for (int off = 256; off > 0; off >>= 1) {
        if (tid < off) {
            float ov = red[tid+off]; int oi = redi[tid+off];
            if (ov > red[tid] || (ov == red[tid] && oi < redi[tid])) {
                red[tid] = ov; redi[tid] = oi;
            }
        }
        __syncthreads();
    }
    if (tid == 0) { s_bv = red[0]; s_bi = redi[0]; }
    __threadfence();
    __syncthreads();

    // ---- scatter pointer mass ----
    int vv = 0; float a = 0.f;
    if (tid < SSZ) {
        a = att[tid];
        if (a != 0.f) {
            vv = xs[tid];
            atomicAdd(ob + vv, (1.f - pg)*a);
        }
    }
    __threadfence();
    __syncthreads();

    // ---- final argmax over scattered candidates + base ----
    float cv = -1.f; int ci = 0x7fffffff;
    if (tid < SSZ && a != 0.f) {
        cv = atomicAdd(ob + vv, 0.f);
        ci = vv;
    }
    red[tid] = cv; redi[tid] = ci; __syncthreads();
    #pragma unroll
    for (int off = 256; off > 0; off >>= 1) {
        if (tid < off) {
            float ov = red[tid+off]; int oi = redi[tid+off];
            if (ov > red[tid] || (ov == red[tid] && oi < redi[tid])) {
                red[tid] = ov; redi[tid] = oi;
            }
        }
        __syncthreads();
    }
    if (tid == 0) {
        float fv = red[0]; int fi = redi[0];
        if (s_bv > fv || (s_bv == fv && s_bi < fi)) { fv = s_bv; fi = s_bi; }
        s_widx = fi;
    }
    __syncthreads();
    int widx = s_widx;
    g_w[(size_t)r*HSZ + tid] = emb[(size_t)widx*HSZ + tid];
}

extern "C" void kernel_launch(void* const* d_in, const int* in_sizes, int n_in,
                              void* d_out, int out_size) {
    const int*   x     = (const int*)  d_in[0];
    const float* enc   = (const float*)d_in[1];
    const float* ehid  = (const float*)d_in[2];
    /* d_in[3] = max_len (constant TSZ=8) */
    const float* emb   = (const float*)d_in[4];
    const float* slot  = (const float*)d_in[5];
    const float* Wih   = (const float*)d_in[6];
    const float* Whh   = (const float*)d_in[7];
    const float* bih   = (const float*)d_in[8];
    const float* bhh   = (const float*)d_in[9];
    const float* wgenW = (const float*)d_in[10];
    const float* wgenb = (const float*)d_in[11];
    const float* actW  = (const float*)d_in[12];
    const float* actb  = (const float*)d_in[13];
    float* out = (float*)d_out;
    const int ptoff = BSZ*JSZ*NOPS;

    cudaFuncSetAttribute(k_vocab_wmma, cudaFuncAttributeMaxDynamicSharedMemorySize, VW_SMEM);

    k_init<<<(RSZ*HSZ + 255)/256, 256>>>(slot, ehid);
    k_split_emb<<<(int)(((size_t)VPAD*HSZ + 255)/256), 256>>>(emb);
    for (int t = 0; t < TSZ; t++) {
        int parity = t & 1;
        k_gru_gemm<<<dim3(24,2,4), 256>>>(Wih, Whh, parity);
        k_gru_gate<<<RSZ, 512>>>(bih, bhh, parity);
        k_vocab_wmma<<<NCTA, 256, VW_SMEM>>>();
        k_attn_softmax<<<RSZ, 512>>>(x, enc, wgenW, wgenb, actW, actb, emb, out,
                                     t == 0, parity, t, ptoff);
    }
}

// round 9
// speedup vs baseline: 1.1034x; 1.1034x over previous
#include <cuda_runtime.h>
#include <cuda_bf16.h>
#include <mma.h>
#include <cstdint>
#include <cstddef>
#include <math.h>
#include <float.h>

using namespace nvcuda;

#define VSZ 30000
#define VPAD 30080
#define HSZ 512
#define BSZ 16
#define SSZ 256
#define JSZ 10
#define TSZ 8
#define NOPS 4
#define RSZ (JSZ*BSZ)
#define NEGV (-1e9f)
#define NCTA 235
#define GH (3*HSZ)   /* 1536 */

// fp32 state
__device__ float g_w[RSZ*HSZ];
__device__ float g_hA[RSZ*HSZ];
__device__ float g_hB[RSZ*HSZ];
__device__ float g_part[4*RSZ*GH];   // [kz*2+sel][r][n<1536]
__device__ float g_logits[RSZ*VSZ];
// bf16 hi/lo splits
__device__ __nv_bfloat16 g_ehi[(size_t)VPAD*HSZ];
__device__ __nv_bfloat16 g_elo[(size_t)VPAD*HSZ];
__device__ __nv_bfloat16 g_hh[RSZ*HSZ];
__device__ __nv_bfloat16 g_hl[RSZ*HSZ];
__device__ __nv_bfloat16 g_wh[RSZ*HSZ];
__device__ __nv_bfloat16 g_wl[RSZ*HSZ];
__device__ __nv_bfloat16 g_wihh[GH*HSZ];
__device__ __nv_bfloat16 g_wihl[GH*HSZ];
__device__ __nv_bfloat16 g_whhh[GH*HSZ];
__device__ __nv_bfloat16 g_whhl[GH*HSZ];

// ---------------- helpers ----------------
__device__ __forceinline__ uint32_t smem_to_u32(const void* smem_ptr) {
    uint32_t addr;
    asm("{ .reg .u64 tmp; cvta.to.shared.u64 tmp, %1; cvt.u32.u64 %0, tmp; }"
        : "=r"(addr) : "l"(smem_ptr));
    return addr;
}
__device__ __forceinline__ void cp_async16(uint32_t saddr, const void* gptr) {
    asm volatile("cp.async.cg.shared.global [%0], [%1], 16;"
                 :: "r"(saddr), "l"(gptr) : "memory");
}
#define CP_COMMIT() asm volatile("cp.async.commit_group;" ::: "memory")
#define CP_WAIT0()  asm volatile("cp.async.wait_group 0;" ::: "memory")

// ---------------- setup: init state + all bf16 splits ----------------
__global__ __launch_bounds__(256)
void k_setup(const float* __restrict__ slot, const float* __restrict__ ehid,
             const float* __restrict__ emb, const float* __restrict__ Wih,
             const float* __restrict__ Whh) {
    size_t stride = (size_t)gridDim.x * blockDim.x;
    for (size_t i = (size_t)blockIdx.x*blockDim.x + threadIdx.x;
         i < (size_t)VPAD*HSZ; i += stride) {
        size_t row = i / HSZ;
        float v = (row < VSZ) ? emb[i] : 0.f;
        __nv_bfloat16 hi = __float2bfloat16_rn(v);
        g_ehi[i] = hi;
        g_elo[i] = __float2bfloat16_rn(v - __bfloat162float(hi));
        if (i < (size_t)RSZ*HSZ) {
            int r = (int)(i / HSZ), h = (int)(i - (size_t)r*HSZ);
            int j = r / BSZ, b = r - j*BSZ;
            float wv = slot[j*HSZ + h];
            g_w[i] = wv;
            __nv_bfloat16 whi = __float2bfloat16_rn(wv);
            g_wh[i] = whi;
            g_wl[i] = __float2bfloat16_rn(wv - __bfloat162float(whi));
            float hv = ehid[b*HSZ + h];
            g_hA[i] = hv;
            __nv_bfloat16 hhi = __float2bfloat16_rn(hv);
            g_hh[i] = hhi;
            g_hl[i] = __float2bfloat16_rn(hv - __bfloat162float(hhi));
        }
        if (i < (size_t)GH*HSZ) {
            float a = Wih[i];
            __nv_bfloat16 ah = __float2bfloat16_rn(a);
            g_wihh[i] = ah;
            g_wihl[i] = __float2bfloat16_rn(a - __bfloat162float(ah));
            float c = Whh[i];
            __nv_bfloat16 ch = __float2bfloat16_rn(c);
            g_whhh[i] = ch;
            g_whhl[i] = __float2bfloat16_rn(c - __bfloat162float(ch));
        }
    }
}

// ---------------- shared wmma tile constants ----------------
#define LDA 72
#define A_SPL (128*LDA*2)
#define B_SPL (160*LDA*2)
#define OFF_AHI 0
#define OFF_ALO (A_SPL)
#define OFF_BHI (2*A_SPL)
#define OFF_BLO (2*A_SPL + B_SPL)
#define SBUF    (2*A_SPL + 2*B_SPL)
#define VW_SMEM (2*SBUF)

// ---------------- wmma bf16 GRU GEMM ----------------
// grid (12, 2, 2): x = 128-wide weight-row tile over 1536; y = sel (0: w@Wih^T,
// 1: h@Whh^T); z = k half (256). Output partial D^T -> g_part[(z*2+sel)][r][n]
__global__ __launch_bounds__(256)
void k_gru_wmma() {
    extern __shared__ char smem[];
    uint32_t sb = smem_to_u32(smem);
    int tid = threadIdx.x, wid = tid >> 5;
    int wr = wid >> 1, wc = wid & 1;
    int n0 = blockIdx.x * 128;
    int sel = blockIdx.y, kz = blockIdx.z;

    const uint4* Whi = (const uint4*)(sel ? g_whhh : g_wihh);
    const uint4* Wlo = (const uint4*)(sel ? g_whhl : g_wihl);
    const uint4* Bhi = (const uint4*)(sel ? g_hh : g_wh);
    const uint4* Blo = (const uint4*)(sel ? g_hl : g_wl);

    wmma::fragment<wmma::accumulator, 16, 16, 16, float> acc[2][5];
    #pragma unroll
    for (int i = 0; i < 2; i++)
        #pragma unroll
        for (int j = 0; j < 5; j++) wmma::fill_fragment(acc[i][j], 0.f);

    {
        uint32_t base = sb;
        int ck = kz*4;
        #pragma unroll
        for (int it = 0; it < 4; it++) {
            int idx = tid + 256*it;
            int row = idx >> 3, q = idx & 7;
            uint32_t so = (uint32_t)(row*LDA + q*8) * 2u;
            size_t gi = ((size_t)(n0 + row)) * 64 + (size_t)(ck*8 + q);
            cp_async16(base + OFF_AHI + so, Whi + gi);
            cp_async16(base + OFF_ALO + so, Wlo + gi);
        }
        #pragma unroll
        for (int it = 0; it < 5; it++) {
            int idx = tid + 256*it;
            if (idx < 1280) {
                int row = idx >> 3, q = idx & 7;
                uint32_t so = (uint32_t)(row*LDA + q*8) * 2u;
                size_t gi = (size_t)row * 64 + (size_t)(ck*8 + q);
                cp_async16(base + OFF_BHI + so, Bhi + gi);
                cp_async16(base + OFF_BLO + so, Blo + gi);
            }
        }
        CP_COMMIT();
    }

    for (int c = 0; c < 4; c++) {
        CP_WAIT0();
        __syncthreads();
        if (c < 3) {
            uint32_t base = sb + ((c + 1) & 1) * SBUF;
            int ck = kz*4 + c + 1;
            #pragma unroll
            for (int it = 0; it < 4; it++) {
                int idx = tid + 256*it;
                int row = idx >> 3, q = idx & 7;
                uint32_t so = (uint32_t)(row*LDA + q*8) * 2u;
                size_t gi = ((size_t)(n0 + row)) * 64 + (size_t)(ck*8 + q);
                cp_async16(base + OFF_AHI + so, Whi + gi);
                cp_async16(base + OFF_ALO + so, Wlo + gi);
            }
            #pragma unroll
            for (int it = 0; it < 5; it++) {
                int idx = tid + 256*it;
                if (idx < 1280) {
                    int row = idx >> 3, q = idx & 7;
                    uint32_t so = (uint32_t)(row*LDA + q*8) * 2u;
                    size_t gi = (size_t)row * 64 + (size_t)(ck*8 + q);
                    cp_async16(base + OFF_BHI + so, Bhi + gi);
                    cp_async16(base + OFF_BLO + so, Blo + gi);
                }
            }
            CP_COMMIT();
        }
        const __nv_bfloat16* pAhi = (const __nv_bfloat16*)(smem + (c & 1)*SBUF + OFF_AHI);
        const __nv_bfloat16* pAlo = (const __nv_bfloat16*)(smem + (c & 1)*SBUF + OFF_ALO);
        const __nv_bfloat16* pBhi = (const __nv_bfloat16*)(smem + (c & 1)*SBUF + OFF_BHI);
        const __nv_bfloat16* pBlo = (const __nv_bfloat16*)(smem + (c & 1)*SBUF + OFF_BLO);
        #pragma unroll
        for (int kk = 0; kk < 4; kk++) {
            wmma::fragment<wmma::matrix_a, 16, 16, 16, __nv_bfloat16, wmma::row_major> a0h, a1h, a0l, a1l;
            wmma::load_matrix_sync(a0h, pAhi + (wr*32)      * LDA + kk*16, LDA);
            wmma::load_matrix_sync(a1h, pAhi + (wr*32 + 16) * LDA + kk*16, LDA);
            wmma::load_matrix_sync(a0l, pAlo + (wr*32)      * LDA + kk*16, LDA);
            wmma::load_matrix_sync(a1l, pAlo + (wr*32 + 16) * LDA + kk*16, LDA);
            #pragma unroll
            for (int j = 0; j < 5; j++) {
                int nb = wc*80 + j*16;
                wmma::fragment<wmma::matrix_b, 16, 16, 16, __nv_bfloat16, wmma::col_major> bh, bl;
                wmma::load_matrix_sync(bh, pBhi + nb*LDA + kk*16, LDA);
                wmma::mma_sync(acc[0][j], a0h, bh, acc[0][j]);
                wmma::mma_sync(acc[1][j], a1h, bh, acc[1][j]);
                wmma::mma_sync(acc[0][j], a0l, bh, acc[0][j]);
                wmma::mma_sync(acc[1][j], a1l, bh, acc[1][j]);
                wmma::load_matrix_sync(bl, pBlo + nb*LDA + kk*16, LDA);
                wmma::mma_sync(acc[0][j], a0h, bl, acc[0][j]);
                wmma::mma_sync(acc[1][j], a1h, bl, acc[1][j]);
            }
        }
        __syncthreads();
    }

    // store D[m=weight row][n=r] -> g_part[(kz*2+sel)][r][n0+m]
    float* base = g_part + (size_t)(kz*2 + sel)*RSZ*GH + n0;
    #pragma unroll
    for (int i = 0; i < 2; i++) {
        int m0 = wr*32 + i*16;
        #pragma unroll
        for (int j = 0; j < 5; j++)
            wmma::store_matrix_sync(base + (size_t)(wc*80 + j*16)*GH + m0,
                                    acc[i][j], GH, wmma::mem_col_major);
    }
}

// ---------------- GRU gate + h bf16 split ----------------
__global__ __launch_bounds__(512)
void k_gru_gate(const float* __restrict__ bih,
                const float* __restrict__ bhh, int parity) {
    const float* __restrict__ hold = parity ? g_hB : g_hA;
    float* __restrict__ hnew = parity ? g_hA : g_hB;
    int r = blockIdx.x, c = threadIdx.x;
    size_t ro = (size_t)r*GH;
    const float* P0 = g_part;                        // kz0 sel0
    const float* P1 = g_part + (size_t)RSZ*GH;       // kz0 sel1
    const float* P2 = g_part + (size_t)2*RSZ*GH;     // kz1 sel0
    const float* P3 = g_part + (size_t)3*RSZ*GH;     // kz1 sel1
    float ir  = P0[ro+c]      + P2[ro+c]      + bih[c];
    float iz  = P0[ro+512+c]  + P2[ro+512+c]  + bih[512+c];
    float inn = P0[ro+1024+c] + P2[ro+1024+c] + bih[1024+c];
    float hr  = P1[ro+c]      + P3[ro+c]      + bhh[c];
    float hz  = P1[ro+512+c]  + P3[ro+512+c]  + bhh[512+c];
    float hn  = P1[ro+1024+c] + P3[ro+1024+c] + bhh[1024+c];
    float rg = 1.f/(1.f+expf(-(ir+hr)));
    float zg = 1.f/(1.f+expf(-(iz+hz)));
    float ng = tanhf(inn + rg*hn);
    float v = (1.f-zg)*ng + zg*hold[r*HSZ+c];
    hnew[r*HSZ+c] = v;
    __nv_bfloat16 hi = __float2bfloat16_rn(v);
    g_hh[r*HSZ+c] = hi;
    g_hl[r*HSZ+c] = __float2bfloat16_rn(v - __bfloat162float(hi));
}

// ---------------- wmma bf16 vocab GEMM (R7 direct-store epilogue) --------
__global__ __launch_bounds__(256)
void k_vocab_wmma() {
    extern __shared__ char smem[];
    uint32_t sb = smem_to_u32(smem);
    int tid = threadIdx.x, wid = tid >> 5;
    int wr = wid >> 1, wc = wid & 1;
    size_t vbase = (size_t)blockIdx.x * 128;

    const uint4* Ehi = (const uint4*)g_ehi;
    const uint4* Elo = (const uint4*)g_elo;
    const uint4* Hhi = (const uint4*)g_hh;
    const uint4* Hlo = (const uint4*)g_hl;

    wmma::fragment<wmma::accumulator, 16, 16, 16, float> acc[2][5];
    #pragma unroll
    for (int i = 0; i < 2; i++)
        #pragma unroll
        for (int j = 0; j < 5; j++) wmma::fill_fragment(acc[i][j], 0.f);

    {
        uint32_t base = sb;
        #pragma unroll
        for (int it = 0; it < 4; it++) {
            int idx = tid + 256*it;
            int row = idx >> 3, q = idx & 7;
            uint32_t so = (uint32_t)(row*LDA + q*8) * 2u;
            size_t gi = (vbase + (size_t)row) * 64 + (size_t)q;
            cp_async16(base + OFF_AHI + so, Ehi + gi);
            cp_async16(base + OFF_ALO + so, Elo + gi);
        }
        #pragma unroll
        for (int it = 0; it < 5; it++) {
            int idx = tid + 256*it;
            if (idx < 1280) {
                int row = idx >> 3, q = idx & 7;
                uint32_t so = (uint32_t)(row*LDA + q*8) * 2u;
                size_t gi = (size_t)row * 64 + (size_t)q;
                cp_async16(base + OFF_BHI + so, Hhi + gi);
                cp_async16(base + OFF_BLO + so, Hlo + gi);
            }
        }
        CP_COMMIT();
    }

    for (int c = 0; c < 8; c++) {
        CP_WAIT0();
        __syncthreads();
        if (c < 7) {
            uint32_t base = sb + ((c + 1) & 1) * SBUF;
            int cq = (c + 1) * 8;
            #pragma unroll
            for (int it = 0; it < 4; it++) {
                int idx = tid + 256*it;
                int row = idx >> 3, q = idx & 7;
                uint32_t so = (uint32_t)(row*LDA + q*8) * 2u;
                size_t gi = (vbase + (size_t)row) * 64 + (size_t)(cq + q);
                cp_async16(base + OFF_AHI + so, Ehi + gi);
                cp_async16(base + OFF_ALO + so, Elo + gi);
            }
            #pragma unroll
            for (int it = 0; it < 5; it++) {
                int idx = tid + 256*it;
                if (idx < 1280) {
                    int row = idx >> 3, q = idx & 7;
                    uint32_t so = (uint32_t)(row*LDA + q*8) * 2u;
                    size_t gi = (size_t)row * 64 + (size_t)(cq + q);
                    cp_async16(base + OFF_BHI + so, Hhi + gi);
                    cp_async16(base + OFF_BLO + so, Hlo + gi);
                }
            }
            CP_COMMIT();
        }
        const __nv_bfloat16* pAhi = (const __nv_bfloat16*)(smem + (c & 1)*SBUF + OFF_AHI);
        const __nv_bfloat16* pAlo = (const __nv_bfloat16*)(smem + (c & 1)*SBUF + OFF_ALO);
        const __nv_bfloat16* pBhi = (const __nv_bfloat16*)(smem + (c & 1)*SBUF + OFF_BHI);
        const __nv_bfloat16* pBlo = (const __nv_bfloat16*)(smem + (c & 1)*SBUF + OFF_BLO);
        #pragma unroll
        for (int kk = 0; kk < 4; kk++) {
            wmma::fragment<wmma::matrix_a, 16, 16, 16, __nv_bfloat16, wmma::row_major> a0h, a1h, a0l, a1l;
            wmma::load_matrix_sync(a0h, pAhi + (wr*32)      * LDA + kk*16, LDA);
            wmma::load_matrix_sync(a1h, pAhi + (wr*32 + 16) * LDA + kk*16, LDA);
            wmma::load_matrix_sync(a0l, pAlo + (wr*32)      * LDA + kk*16, LDA);
            wmma::load_matrix_sync(a1l, pAlo + (wr*32 + 16) * LDA + kk*16, LDA);
            #pragma unroll
            for (int j = 0; j < 5; j++) {
                int nb = wc*80 + j*16;
                wmma::fragment<wmma::matrix_b, 16, 16, 16, __nv_bfloat16, wmma::col_major> bh, bl;
                wmma::load_matrix_sync(bh, pBhi + nb*LDA + kk*16, LDA);
                wmma::mma_sync(acc[0][j], a0h, bh, acc[0][j]);
                wmma::mma_sync(acc[1][j], a1h, bh, acc[1][j]);
                wmma::mma_sync(acc[0][j], a0l, bh, acc[0][j]);
                wmma::mma_sync(acc[1][j], a1l, bh, acc[1][j]);
                wmma::load_matrix_sync(bl, pBlo + nb*LDA + kk*16, LDA);
                wmma::mma_sync(acc[0][j], a0h, bl, acc[0][j]);
                wmma::mma_sync(acc[1][j], a1h, bl, acc[1][j]);
            }
        }
        __syncthreads();
    }

    #pragma unroll
    for (int i = 0; i < 2; i++) {
        size_t v0 = vbase + (size_t)(wr*32 + i*16);
        if (v0 + 16 <= VSZ) {
            #pragma unroll
            for (int j = 0; j < 5; j++) {
                int n0 = wc*80 + j*16;
                wmma::store_matrix_sync(g_logits + (size_t)n0*VSZ + v0,
                                        acc[i][j], VSZ, wmma::mem_col_major);
            }
        }
    }
}

// ---------------- fused attn + softmax + scatter + argmax + next-w --------
__global__ __launch_bounds__(512)
void k_attn_softmax(const int* __restrict__ x, const float* __restrict__ enc,
                    const float* __restrict__ wgenW, const float* __restrict__ wgenb,
                    const float* __restrict__ actW, const float* __restrict__ actb,
                    const float* __restrict__ emb, float* __restrict__ out,
                    int is_t0, int parity, int t, int ptoff) {
    const float* __restrict__ hnew = parity ? g_hA : g_hB;
    int r = blockIdx.x, tid = threadIdx.x, lane = tid & 31, warp = tid >> 5;
    int j = r / BSZ, b = r % BSZ;
    __shared__ float hs[HSZ];
    __shared__ float att[SSZ];
    __shared__ int   xs[SSZ];
    __shared__ float red[512];
    __shared__ int   redi[512];
    __shared__ float s_pg, s_bv;
    __shared__ int   s_bi, s_widx;

    hs[tid] = hnew[(size_t)r*HSZ + tid];
    if (tid < SSZ) xs[tid] = x[b*SSZ + tid];
    __syncthreads();

    // attention scores
    const float4* hv = (const float4*)hs;
    float4 h0 = hv[lane], h1 = hv[lane+32], h2 = hv[lane+64], h3 = hv[lane+96];
    #pragma unroll 4
    for (int i = 0; i < 16; i++) {
        int s = warp*16 + i;
        const float4* ev = (const float4*)(enc + ((size_t)b*SSZ + s)*HSZ);
        float4 e0 = ev[lane], e1 = ev[lane+32], e2 = ev[lane+64], e3 = ev[lane+96];
        float v = e0.x*h0.x + e0.y*h0.y + e0.z*h0.z + e0.w*h0.w
                + e1.x*h1.x + e1.y*h1.y + e1.z*h1.z + e1.w*h1.w
                + e2.x*h2.x + e2.y*h2.y + e2.z*h2.z + e2.w*h2.w
                + e3.x*h3.x + e3.y*h3.y + e3.z*h3.z + e3.w*h3.w;
        #pragma unroll
        for (int off = 16; off > 0; off >>= 1)
            v += __shfl_xor_sync(0xffffffffu, v, off);
        if (lane == 0) att[s] = (xs[s] == 0) ? NEGV : v;
    }
    __syncthreads();

    // softmax over S
    float mv = (tid < SSZ) ? att[tid] : -FLT_MAX;
    red[tid] = mv; __syncthreads();
    #pragma unroll
    for (int off = 256; off > 0; off >>= 1) {
        if (tid < off) red[tid] = fmaxf(red[tid], red[tid+off]);
        __syncthreads();
    }
    float amx = red[0]; __syncthreads();
    float ex = (tid < SSZ) ? expf(mv - amx) : 0.f;
    red[tid] = ex; __syncthreads();
    #pragma unroll
    for (int off = 256; off > 0; off >>= 1) {
        if (tid < off) red[tid] += red[tid+off];
        __syncthreads();
    }
    float ainv = 1.f/red[0]; __syncthreads();
    if (tid < SSZ) att[tid] = ex*ainv;
    __syncthreads();

    // context
    float ctx = 0.f;
    const float* eb = enc + (size_t)b*SSZ*HSZ + tid;
    #pragma unroll 8
    for (int s = 0; s < SSZ; s++) ctx += att[s]*eb[(size_t)s*HSZ];

    // p_gen
    float pv = g_w[(size_t)r*HSZ+tid]*wgenW[tid]
             + hs[tid]*wgenW[HSZ+tid]
             + ctx*wgenW[2*HSZ+tid];
    red[tid] = pv; __syncthreads();
    #pragma unroll
    for (int off = 256; off > 0; off >>= 1) {
        if (tid < off) red[tid] += red[tid+off];
        __syncthreads();
    }
    if (tid == 0) s_pg = 1.f/(1.f+expf(-(red[0] + wgenb[0])));

    // gate head at t==0
    if (is_t0) {
        #pragma unroll
        for (int op = 0; op < NOPS; op++) {
            __syncthreads();
            red[tid] = ctx*actW[op*HSZ + tid]; __syncthreads();
            #pragma unroll
            for (int off = 256; off > 0; off >>= 1) {
                if (tid < off) red[tid] += red[tid+off];
                __syncthreads();
            }
            if (tid == 0) out[b*JSZ*NOPS + j*NOPS + op] = red[0] + actb[op];
        }
    }
    __syncthreads();

    // vocab softmax: max pass
    const float4* __restrict__ L4 = (const float4*)(g_logits + (size_t)r*VSZ);
    float mx = -FLT_MAX;
    for (int i = tid; i < VSZ/4; i += 512) {
        float4 q = L4[i];
        mx = fmaxf(mx, fmaxf(fmaxf(q.x, q.y), fmaxf(q.z, q.w)));
    }
    red[tid] = mx; __syncthreads();
    #pragma unroll
    for (int off = 256; off > 0; off >>= 1) {
        if (tid < off) red[tid] = fmaxf(red[tid], red[tid+off]);
        __syncthreads();
    }
    mx = red[0]; __syncthreads();

    // sum pass
    float sm = 0.f;
    for (int i = tid; i < VSZ/4; i += 512) {
        float4 q = L4[i];
        sm += expf(q.x-mx) + expf(q.y-mx) + expf(q.z-mx) + expf(q.w-mx);
    }
    red[tid] = sm; __syncthreads();
    #pragma unroll
    for (int off = 256; off > 0; off >>= 1) {
        if (tid < off) red[tid] += red[tid+off];
        __syncthreads();
    }
    sm = red[0]; __syncthreads();

    float pg = s_pg;
    float scale = pg / sm;
    float* ob = out + ptoff + ((size_t)(b*JSZ + j)*TSZ + t)*VSZ;
    float4* ob4 = (float4*)ob;

    // write pass + base argmax
    float bv = -1.f; int bi = 0;
    for (int i = tid; i < VSZ/4; i += 512) {
        float4 q = L4[i];
        float4 p;
        p.x = expf(q.x-mx)*scale; p.y = expf(q.y-mx)*scale;
        p.z = expf(q.z-mx)*scale; p.w = expf(q.w-mx)*scale;
        ob4[i] = p;
        if (p.x > bv) { bv = p.x; bi = 4*i; }
        if (p.y > bv) { bv = p.y; bi = 4*i+1; }
        if (p.z > bv) { bv = p.z; bi = 4*i+2; }
        if (p.w > bv) { bv = p.w; bi = 4*i+3; }
    }
    red[tid] = bv; redi[tid] = bi; __syncthreads();
    #pragma unroll
    for (int off = 256; off > 0; off >>= 1) {
        if (tid < off) {
            float ov = red[tid+off]; int oi = redi[tid+off];
            if (ov > red[tid] || (ov == red[tid] && oi < redi[tid])) {
                red[tid] = ov; redi[tid] = oi;
            }
        }
        __syncthreads();
    }
    if (tid == 0) { s_bv = red[0]; s_bi = redi[0]; }
    __threadfence();
    __syncthreads();

    // scatter pointer mass
    int vv = 0; float a = 0.f;
    if (tid < SSZ) {
        a = att[tid];
        if (a != 0.f) {
            vv = xs[tid];
            atomicAdd(ob + vv, (1.f - pg)*a);
        }
    }
    __threadfence();
    __syncthreads();

    // final argmax
    float cv = -1.f; int ci = 0x7fffffff;
    if (tid < SSZ && a != 0.f) {
        cv = atomicAdd(ob + vv, 0.f);
        ci = vv;
    }
    red[tid] = cv; redi[tid] = ci; __syncthreads();
    #pragma unroll
    for (int off = 256; off > 0; off >>= 1) {
        if (tid < off) {
            float ov = red[tid+off]; int oi = redi[tid+off];
            if (ov > red[tid] || (ov == red[tid] && oi < redi[tid])) {
                red[tid] = ov; redi[tid] = oi;
            }
        }
        __syncthreads();
    }
    if (tid == 0) {
        float fv = red[0]; int fi = redi[0];
        if (s_bv > fv || (s_bv == fv && s_bi < fi)) { fv = s_bv; fi = s_bi; }
        s_widx = fi;
    }
    __syncthreads();
    int widx = s_widx;
    g_w[(size_t)r*HSZ + tid] = emb[(size_t)widx*HSZ + tid];
    g_wh[(size_t)r*HSZ + tid] = g_ehi[(size_t)widx*HSZ + tid];
    g_wl[(size_t)r*HSZ + tid] = g_elo[(size_t)widx*HSZ + tid];
}

extern "C" void kernel_launch(void* const* d_in, const int* in_sizes, int n_in,
                              void* d_out, int out_size) {
    const int*   x     = (const int*)  d_in[0];
    const float* enc   = (const float*)d_in[1];
    const float* ehid  = (const float*)d_in[2];
    /* d_in[3] = max_len (constant TSZ=8) */
    const float* emb   = (const float*)d_in[4];
    const float* slot  = (const float*)d_in[5];
    const float* Wih   = (const float*)d_in[6];
    const float* Whh   = (const float*)d_in[7];
    const float* bih   = (const float*)d_in[8];
    const float* bhh   = (const float*)d_in[9];
    const float* wgenW = (const float*)d_in[10];
    const float* wgenb = (const float*)d_in[11];
    const float* actW  = (const float*)d_in[12];
    const float* actb  = (const float*)d_in[13];
    float* out = (float*)d_out;
    const int ptoff = BSZ*JSZ*NOPS;

    cudaFuncSetAttribute(k_vocab_wmma, cudaFuncAttributeMaxDynamicSharedMemorySize, VW_SMEM);
    cudaFuncSetAttribute(k_gru_wmma, cudaFuncAttributeMaxDynamicSharedMemorySize, VW_SMEM);

    k_setup<<<2048, 256>>>(slot, ehid, emb, Wih, Whh);
    for (int t = 0; t < TSZ; t++) {
        int parity = t & 1;
        k_gru_wmma<<<dim3(12,2,2), 256, VW_SMEM>>>();
        k_gru_gate<<<RSZ, 512>>>(bih, bhh, parity);
        k_vocab_wmma<<<NCTA, 256, VW_SMEM>>>();
        k_attn_softmax<<<RSZ, 512>>>(x, enc, wgenW, wgenb, actW, actb, emb, out,
                                     t == 0, parity, t, ptoff);
    }
}